// round 16
// baseline (speedup 1.0000x reference)
#include <cuda_runtime.h>
#include <math_constants.h>
#include <float.h>

// Problem shape (fixed): B=32, H=16, N=1024, D=128, fp32.
// IDENTITY: softmax is shift-invariant per (b,h) => attn depends only on
// dot(t[n], w2). transformer_t_1 / w1 / concat_b are never read.
//
// NON-persistent fused kernel: 512 blocks x 512 threads, ONE bh per block.
// CLC keeps ~148 resident (regs~72 -> 1 block/SM), so all 148 SMs work and
// the L2 re-read window stays ~148 concurrent bh (~75-110 MB < 126 MB L2).
// pass1 (DRAM stream + online (m,sum) in registers) -> tiny softmax combine
// -> pass2 (re-read t[bh] as L2 hits, write out evict-first).
// Dataset guarantee: lengths in [N/2, N] => padd >= 512.
#define Bc 32
#define Hc 16
#define Nc 1024
#define Dc 128
#define D4 (Dc / 4)                 // 32 float4 per row
#define NBH (Bc * Hc)               // 512
#define NTH 512

__global__ __launch_bounds__(NTH, 1)
void fused_kernel(const float* __restrict__ t,
                  const int*   __restrict__ padding,
                  const float* __restrict__ w,      // [256]: w1 | w2
                  float*       __restrict__ out)
{
    __shared__ float  s_sc[Nc];        // raw scores -> factor (in place)
    __shared__ float2 s_ms[16];        // per-warp (max, sum)
    __shared__ int    s_pd[16];        // per-warp padd min

    const int bh   = blockIdx.x;
    const int tid  = threadIdx.x;
    const int wid  = tid >> 5;
    const int lane = tid & 31;
    const int g    = lane >> 3;
    const int sub  = lane & 7;

    const float4* wf = reinterpret_cast<const float4*>(w);
    const float4 u0 = wf[D4 + sub];
    const float4 u1 = wf[D4 + sub + 8];
    const float4 u2 = wf[D4 + sub + 16];
    const float4 u3 = wf[D4 + sub + 24];

    const float4* tb = reinterpret_cast<const float4*>(t) + (size_t)bh * Nc * D4;

    // ---- padd for this bh's batch (b = bh / Hc) ----
    {
        const int* pb = padding + (bh >> 4) * Nc;
        int local = Nc;
        if (pb[tid] == 0)       local = tid;
        if (pb[tid + 512] == 0) local = min(local, tid + 512);
        #pragma unroll
        for (int o = 16; o > 0; o >>= 1)
            local = min(local, __shfl_xor_sync(0xffffffffu, local, o));
        if (lane == 0) s_pd[wid] = local;
    }
    // (no barrier needed yet; padd consumed after [B1])

    // ---- pass 1: scores -> s_sc, ONLINE (m, sum) in registers ----
    float om = -FLT_MAX;
    float os = 0.f;
    float my_sc[16];                   // this lane's row score per iteration
    #pragma unroll 2
    for (int it = 0; it < 16; it++) {
        const int row = it * 64 + wid * 4 + g;
        const float4* trow = tb + row * D4;
        float4 c0 = trow[sub];
        float4 c1 = trow[sub + 8];
        float4 c2 = trow[sub + 16];
        float4 c3 = trow[sub + 24];
        float sc = c0.x*u0.x + c0.y*u0.y + c0.z*u0.z + c0.w*u0.w
                 + c1.x*u1.x + c1.y*u1.y + c1.z*u1.z + c1.w*u1.w
                 + c2.x*u2.x + c2.y*u2.y + c2.z*u2.z + c2.w*u2.w
                 + c3.x*u3.x + c3.y*u3.y + c3.z*u3.z + c3.w*u3.w;
        sc += __shfl_xor_sync(0xffffffffu, sc, 1);
        sc += __shfl_xor_sync(0xffffffffu, sc, 2);
        sc += __shfl_xor_sync(0xffffffffu, sc, 4);
        if (sub == 0) s_sc[row] = sc;
        my_sc[it] = sc;                // kept to avoid re-touching smem later
    }
    __syncthreads();                   // [B1] s_sc + s_pd visible
    int padd = Nc;
    #pragma unroll
    for (int k = 0; k < 16; k++) padd = min(padd, s_pd[k]);

    // online (m, sum) over this lane's 16 rows, masked by padd
    #pragma unroll
    for (int it = 0; it < 16; it++) {
        const int row = it * 64 + wid * 4 + g;
        if (row < padd) {
            float sc = my_sc[it];
            float nm = fmaxf(om, sc);
            os = os * __expf(om - nm) + __expf(sc - nm);
            om = nm;
        }
    }
    // combine the 4 g-groups within the warp
    #pragma unroll
    for (int o = 8; o <= 16; o <<= 1) {
        float m2 = __shfl_xor_sync(0xffffffffu, om, o);
        float s2 = __shfl_xor_sync(0xffffffffu, os, o);
        float nm = fmaxf(om, m2);
        os = os * __expf(om - nm) + s2 * __expf(m2 - nm);
        om = nm;
    }
    if (lane == 0) s_ms[wid] = make_float2(om, os);
    __syncthreads();                   // [B2] s_ms ready

    // ---- tiny softmax finish: 16-elem combine + 2 factor writes ----
    float mx = -FLT_MAX;
    #pragma unroll
    for (int k = 0; k < 16; k++) mx = fmaxf(mx, s_ms[k].x);
    float tot = 0.f;
    #pragma unroll
    for (int k = 0; k < 16; k++)
        tot += s_ms[k].y * __expf(s_ms[k].x - mx);
    const float inv = (tot > 0.f) ? (1.f / tot) : 0.f;

    {
        float v0 = s_sc[tid];          // tid < 512 <= padd always valid
        float v1 = s_sc[tid + 512];
        float f0 = fmaf(__expf(v0 - mx), inv, 1.f);
        float f1 = ((tid + 512) < padd) ? fmaf(__expf(v1 - mx), inv, 1.f) : 1.f;
        s_sc[tid]       = f0;
        s_sc[tid + 512] = f1;
    }
    __syncthreads();                   // [B3] factor ready

    // ---- pass 2: scale (L2 hits), ILP 4, 16 iterations ----
    float4* ob = reinterpret_cast<float4*>(out) + (size_t)bh * Nc * D4;
    #pragma unroll 2
    for (int j = tid; j < Nc * D4; j += NTH * 4) {
        float4 x0 = __ldcs(tb + j);
        float4 x1 = __ldcs(tb + j + NTH);
        float4 x2 = __ldcs(tb + j + NTH * 2);
        float4 x3 = __ldcs(tb + j + NTH * 3);
        float f0 = s_sc[(j)           >> 5];   // warp-uniform LDS
        float f1 = s_sc[(j + NTH)     >> 5];
        float f2 = s_sc[(j + NTH * 2) >> 5];
        float f3 = s_sc[(j + NTH * 3) >> 5];
        x0.x *= f0; x0.y *= f0; x0.z *= f0; x0.w *= f0;
        x1.x *= f1; x1.y *= f1; x1.z *= f1; x1.w *= f1;
        x2.x *= f2; x2.y *= f2; x2.z *= f2; x2.w *= f2;
        x3.x *= f3; x3.y *= f3; x3.z *= f3; x3.w *= f3;
        __stcs(ob + j,           x0);
        __stcs(ob + j + NTH,     x1);
        __stcs(ob + j + NTH * 2, x2);
        __stcs(ob + j + NTH * 3, x3);
    }
}

extern "C" void kernel_launch(void* const* d_in, const int* in_sizes, int n_in,
                              void* d_out, int out_size)
{
    const float* t       = (const float*)d_in[1];
    const int*   padding = (const int*)d_in[2];

    const float* w = nullptr;
    for (int i = 3; i < n_in; i++)
        if (in_sizes[i] == 2 * Dc) { w = (const float*)d_in[i]; }

    fused_kernel<<<NBH, NTH>>>(t, padding, w, (float*)d_out);
    (void)out_size;
}

// round 17
// speedup vs baseline: 1.0755x; 1.0755x over previous
#include <cuda_runtime.h>
#include <math_constants.h>
#include <float.h>

// Problem shape (fixed): B=32, H=16, N=1024, D=128, fp32.
// IDENTITY: softmax is shift-invariant per (b,h) => attn depends only on
// dot(t[n], w2). transformer_t_1 / w1 / concat_b are never read.
//
// Persistent fused kernel: 128 blocks x 512 threads, 4 bh per block,
// SEQUENTIAL pass1 -> tiny softmax -> pass2 per bh (L2 re-read window =
// 128 concurrent bh ~64 MB < 126 MB L2 — the invariant to protect).
// PASS1 MLP = 8: two quads (8 rows) per warp-iteration, 8 independent
// LDG.128 in flight per warp (Little's law: 16 warps x 8 x 512B = 64 KB
// >> 26 KB needed to saturate DRAM at 600-cyc latency).
// Dataset guarantee: lengths in [N/2, N] => padd >= 512.
#define Bc 32
#define Hc 16
#define Nc 1024
#define Dc 128
#define D4 (Dc / 4)                 // 32 float4 per row
#define NBH (Bc * Hc)               // 512
#define NBLK 128
#define BH_PER_BLK 4
#define NTH 512

__global__ __launch_bounds__(NTH, 1)
void fused_kernel(const float* __restrict__ t,
                  const int*   __restrict__ padding,
                  const float* __restrict__ w,      // [256]: w1 | w2
                  float*       __restrict__ out)
{
    __shared__ float  s_sc[Nc];        // raw scores -> factor (in place)
    __shared__ float2 s_ms[16];        // per-warp (max, sum)
    __shared__ int    s_pd[16];        // per-warp padd min (once per block)

    const int tid  = threadIdx.x;
    const int wid  = tid >> 5;
    const int lane = tid & 31;
    const int g    = lane >> 3;
    const int sub  = lane & 7;

    const float4* wf = reinterpret_cast<const float4*>(w);
    const float4 u0 = wf[D4 + sub];
    const float4 u1 = wf[D4 + sub + 8];
    const float4 u2 = wf[D4 + sub + 16];
    const float4 u3 = wf[D4 + sub + 24];

    const int bh0 = blockIdx.x * BH_PER_BLK;

    // ---- padd: same batch b for all 4 bh of this block; compute ONCE ----
    {
        const int* pb = padding + (bh0 >> 4) * Nc;    // b = bh0 / Hc
        int local = Nc;
        if (pb[tid] == 0)       local = tid;
        if (pb[tid + 512] == 0) local = min(local, tid + 512);
        #pragma unroll
        for (int o = 16; o > 0; o >>= 1)
            local = min(local, __shfl_xor_sync(0xffffffffu, local, o));
        if (lane == 0) s_pd[wid] = local;
    }
    __syncthreads();
    int padd = Nc;
    #pragma unroll
    for (int k = 0; k < 16; k++) padd = min(padd, s_pd[k]);

    #pragma unroll 1
    for (int i = 0; i < BH_PER_BLK; i++) {
        const int bh = bh0 + i;
        const float4* tb = reinterpret_cast<const float4*>(t) + (size_t)bh * Nc * D4;

        // ---- pass 1: scores -> s_sc, MLP=8, online (m,sum) in registers ----
        // Each warp: 2 quads (rows wid*8+g and wid*8+4+g) per iteration,
        // 16 warps x 8 rows = 128 rows/iter, 8 iterations.
        float om = -FLT_MAX;
        float os = 0.f;
        #pragma unroll 1
        for (int it = 0; it < 8; it++) {
            const int rowA = it * 128 + wid * 8 + g;
            const int rowB = rowA + 4;
            const float4* ta = tb + rowA * D4;
            const float4* tbp = tb + rowB * D4;
            // 8 independent loads issued back-to-back
            float4 c0 = ta[sub];
            float4 c1 = ta[sub + 8];
            float4 c2 = ta[sub + 16];
            float4 c3 = ta[sub + 24];
            float4 d0 = tbp[sub];
            float4 d1 = tbp[sub + 8];
            float4 d2 = tbp[sub + 16];
            float4 d3 = tbp[sub + 24];

            float scA = c0.x*u0.x + c0.y*u0.y + c0.z*u0.z + c0.w*u0.w
                      + c1.x*u1.x + c1.y*u1.y + c1.z*u1.z + c1.w*u1.w
                      + c2.x*u2.x + c2.y*u2.y + c2.z*u2.z + c2.w*u2.w
                      + c3.x*u3.x + c3.y*u3.y + c3.z*u3.z + c3.w*u3.w;
            float scB = d0.x*u0.x + d0.y*u0.y + d0.z*u0.z + d0.w*u0.w
                      + d1.x*u1.x + d1.y*u1.y + d1.z*u1.z + d1.w*u1.w
                      + d2.x*u2.x + d2.y*u2.y + d2.z*u2.z + d2.w*u2.w
                      + d3.x*u3.x + d3.y*u3.y + d3.z*u3.z + d3.w*u3.w;

            scA += __shfl_xor_sync(0xffffffffu, scA, 1);
            scB += __shfl_xor_sync(0xffffffffu, scB, 1);
            scA += __shfl_xor_sync(0xffffffffu, scA, 2);
            scB += __shfl_xor_sync(0xffffffffu, scB, 2);
            scA += __shfl_xor_sync(0xffffffffu, scA, 4);
            scB += __shfl_xor_sync(0xffffffffu, scB, 4);
            if (sub == 0) { s_sc[rowA] = scA; s_sc[rowB] = scB; }

            if (rowA < padd) {
                float nm = fmaxf(om, scA);
                os = os * __expf(om - nm) + __expf(scA - nm);
                om = nm;
            }
            if (rowB < padd) {
                float nm = fmaxf(om, scB);
                os = os * __expf(om - nm) + __expf(scB - nm);
                om = nm;
            }
        }
        // combine the 4 g-groups within the warp
        #pragma unroll
        for (int o = 8; o <= 16; o <<= 1) {
            float m2 = __shfl_xor_sync(0xffffffffu, om, o);
            float s2 = __shfl_xor_sync(0xffffffffu, os, o);
            float nm = fmaxf(om, m2);
            os = os * __expf(om - nm) + s2 * __expf(m2 - nm);
            om = nm;
        }
        if (lane == 0) s_ms[wid] = make_float2(om, os);
        __syncthreads();                               // [B1] s_sc, s_ms ready

        // ---- tiny softmax finish: 16-elem combine + 2 factor writes ----
        float mx = -FLT_MAX;
        #pragma unroll
        for (int k = 0; k < 16; k++) mx = fmaxf(mx, s_ms[k].x);
        float tot = 0.f;
        #pragma unroll
        for (int k = 0; k < 16; k++)
            tot += s_ms[k].y * __expf(s_ms[k].x - mx);
        const float inv = (tot > 0.f) ? (1.f / tot) : 0.f;

        {
            float v0 = s_sc[tid];                      // tid < 512 <= padd
            float v1 = s_sc[tid + 512];
            float f0 = fmaf(__expf(v0 - mx), inv, 1.f);
            float f1 = ((tid + 512) < padd) ? fmaf(__expf(v1 - mx), inv, 1.f) : 1.f;
            s_sc[tid]       = f0;
            s_sc[tid + 512] = f1;
        }
        __syncthreads();                               // [B2] factor ready

        // ---- pass 2: scale (L2 hits), ILP 4 ----
        float4* ob = reinterpret_cast<float4*>(out) + (size_t)bh * Nc * D4;
        #pragma unroll 2
        for (int j = tid; j < Nc * D4; j += NTH * 4) {
            float4 x0 = __ldcs(tb + j);
            float4 x1 = __ldcs(tb + j + NTH);
            float4 x2 = __ldcs(tb + j + NTH * 2);
            float4 x3 = __ldcs(tb + j + NTH * 3);
            float f0 = s_sc[(j)           >> 5];       // warp-uniform LDS
            float f1 = s_sc[(j + NTH)     >> 5];
            float f2 = s_sc[(j + NTH * 2) >> 5];
            float f3 = s_sc[(j + NTH * 3) >> 5];
            x0.x *= f0; x0.y *= f0; x0.z *= f0; x0.w *= f0;
            x1.x *= f1; x1.y *= f1; x1.z *= f1; x1.w *= f1;
            x2.x *= f2; x2.y *= f2; x2.z *= f2; x2.w *= f2;
            x3.x *= f3; x3.y *= f3; x3.z *= f3; x3.w *= f3;
            __stcs(ob + j,           x0);
            __stcs(ob + j + NTH,     x1);
            __stcs(ob + j + NTH * 2, x2);
            __stcs(ob + j + NTH * 3, x3);
        }
        __syncthreads();                               // [B3] protect s_sc
    }
}

extern "C" void kernel_launch(void* const* d_in, const int* in_sizes, int n_in,
                              void* d_out, int out_size)
{
    const float* t       = (const float*)d_in[1];
    const int*   padding = (const int*)d_in[2];

    const float* w = nullptr;
    for (int i = 3; i < n_in; i++)
        if (in_sizes[i] == 2 * Dc) { w = (const float*)d_in[i]; }

    fused_kernel<<<NBLK, NTH>>>(t, padding, w, (float*)d_out);
    (void)out_size;
}